// round 5
// baseline (speedup 1.0000x reference)
#include <cuda_runtime.h>
#include <cstdint>

#define B_  32
#define T_  2048
#define IN_ 512
#define H_  256
#define NG  32      // groups of 8 presynaptic neurons
#define NP  256     // patterns per group (2^8)

// Scratch (allocation-free rule: __device__ globals)
__device__ float g_proj[(size_t)B_ * T_ * H_];        // 64 MB input projection
__device__ float g_Vt[H_ * H_];                       // Vt[j][h] = V[h][j]
__device__ float g_tab[(size_t)NG * NP * H_];         // 8 MB group subset-sum table

// ---- packed f32x2 helpers (sm_103a FFMA2 — only reachable via PTX) ----
#define PACK2(d, x, y)   asm("mov.b64 %0, {%1, %2};" : "=l"(d) : "f"(x), "f"(y))
#define UNPACK2(x, y, d) asm("mov.b64 {%0, %1}, %2;" : "=f"(x), "=f"(y) : "l"(d))
#define FMA2(d, a, b)    asm("fma.rn.f32x2 %0, %1, %2, %0;" : "+l"(d) : "l"(a), "l"(b))

// ---------------------------------------------------------------------------
// Transpose V (tiny)
// ---------------------------------------------------------------------------
__global__ void transpose_V(const float* __restrict__ V) {
    int j = blockIdx.x;
    int h = threadIdx.x;
    g_Vt[j * H_ + h] = V[h * H_ + j];
}

// ---------------------------------------------------------------------------
// tab[g][p][h] = sum_{i: bit i of p} Vt[8g+i][h]   (ascending i)
// ---------------------------------------------------------------------------
__global__ void build_tab(void) {
    const int blk = blockIdx.x;          // 0..8191
    const int g = blk >> 8;
    const int p = blk & 255;
    const int h = threadIdx.x;
    float s = 0.0f;
    #pragma unroll
    for (int i = 0; i < 8; i++)
        if ((p >> i) & 1)
            s = __fadd_rn(s, g_Vt[(g * 8 + i) * H_ + h]);
    g_tab[((size_t)g * NP + p) * H_ + h] = s;
}

// ---------------------------------------------------------------------------
// proj = x @ W^T + b   (M=65536, N=256, K=512)
// 128x128x16 tiles, 8x8 thread tile, FFMA2 inner loop (32 fma2/kk vs 64 ffma)
// ---------------------------------------------------------------------------
#define GBM 128
#define GBN 128
#define GBK 16

__global__ __launch_bounds__(256, 2) void gemm_proj(
    const float* __restrict__ x, const float* __restrict__ W,
    const float* __restrict__ bia) {
    __shared__ float As[2][GBK][GBM];
    __shared__ float Bs[2][GBK][GBN];
    const int bm = blockIdx.x * GBM;
    const int bn = blockIdx.y * GBN;
    const int tid = threadIdx.x;
    const int tx = tid & 15;
    const int ty = tid >> 4;
    const int lk = (tid & 3) * 4;

    uint64_t acc2[8][4];
    {
        uint64_t z; float zf = 0.0f;
        PACK2(z, zf, zf);
        #pragma unroll
        for (int i = 0; i < 8; i++)
            #pragma unroll
            for (int j = 0; j < 4; j++) acc2[i][j] = z;
    }

    float4 ra[2], rb[2];

    #pragma unroll
    for (int it = 0; it < 2; it++) {
        int m = (it * 256 + tid) >> 2;
        ra[it] = *(const float4*)&x[(size_t)(bm + m) * IN_ + lk];
        rb[it] = *(const float4*)&W[(size_t)(bn + m) * IN_ + lk];
    }
    #pragma unroll
    for (int it = 0; it < 2; it++) {
        int m = (it * 256 + tid) >> 2;
        As[0][lk + 0][m] = ra[it].x; As[0][lk + 1][m] = ra[it].y;
        As[0][lk + 2][m] = ra[it].z; As[0][lk + 3][m] = ra[it].w;
        Bs[0][lk + 0][m] = rb[it].x; Bs[0][lk + 1][m] = rb[it].y;
        Bs[0][lk + 2][m] = rb[it].z; Bs[0][lk + 3][m] = rb[it].w;
    }
    __syncthreads();

    const int NT = IN_ / GBK;
    for (int kt = 0; kt < NT; kt++) {
        const int cur = kt & 1, nxt = cur ^ 1;
        if (kt + 1 < NT) {
            int k0 = (kt + 1) * GBK + lk;
            #pragma unroll
            for (int it = 0; it < 2; it++) {
                int m = (it * 256 + tid) >> 2;
                ra[it] = *(const float4*)&x[(size_t)(bm + m) * IN_ + k0];
                rb[it] = *(const float4*)&W[(size_t)(bn + m) * IN_ + k0];
            }
        }
        #pragma unroll
        for (int kk = 0; kk < GBK; kk++) {
            float a[8];
            float4 b0 = *(const float4*)&Bs[cur][kk][tx * 8];
            float4 b1 = *(const float4*)&Bs[cur][kk][tx * 8 + 4];
            *(float4*)&a[0] = *(const float4*)&As[cur][kk][ty * 8];
            *(float4*)&a[4] = *(const float4*)&As[cur][kk][ty * 8 + 4];
            uint64_t bp[4];
            PACK2(bp[0], b0.x, b0.y);
            PACK2(bp[1], b0.z, b0.w);
            PACK2(bp[2], b1.x, b1.y);
            PACK2(bp[3], b1.z, b1.w);
            #pragma unroll
            for (int i = 0; i < 8; i++) {
                uint64_t aa;
                PACK2(aa, a[i], a[i]);
                FMA2(acc2[i][0], aa, bp[0]);
                FMA2(acc2[i][1], aa, bp[1]);
                FMA2(acc2[i][2], aa, bp[2]);
                FMA2(acc2[i][3], aa, bp[3]);
            }
        }
        if (kt + 1 < NT) {
            #pragma unroll
            for (int it = 0; it < 2; it++) {
                int m = (it * 256 + tid) >> 2;
                As[nxt][lk + 0][m] = ra[it].x; As[nxt][lk + 1][m] = ra[it].y;
                As[nxt][lk + 2][m] = ra[it].z; As[nxt][lk + 3][m] = ra[it].w;
                Bs[nxt][lk + 0][m] = rb[it].x; Bs[nxt][lk + 1][m] = rb[it].y;
                Bs[nxt][lk + 2][m] = rb[it].z; Bs[nxt][lk + 3][m] = rb[it].w;
            }
        }
        __syncthreads();
    }

    float bv[8];
    #pragma unroll
    for (int j = 0; j < 8; j++) bv[j] = bia[bn + tx * 8 + j];
    #pragma unroll
    for (int i = 0; i < 8; i++) {
        int m = bm + ty * 8 + i;
        float o[8];
        #pragma unroll
        for (int j = 0; j < 4; j++)
            UNPACK2(o[2 * j], o[2 * j + 1], acc2[i][j]);
        float4 o0, o1;
        o0.x = o[0] + bv[0]; o0.y = o[1] + bv[1];
        o0.z = o[2] + bv[2]; o0.w = o[3] + bv[3];
        o1.x = o[4] + bv[4]; o1.y = o[5] + bv[5];
        o1.z = o[6] + bv[6]; o1.w = o[7] + bv[7];
        *(float4*)&g_proj[(size_t)m * H_ + bn + tx * 8]     = o0;
        *(float4*)&g_proj[(size_t)m * H_ + bn + tx * 8 + 4] = o1;
    }
}

// ---------------------------------------------------------------------------
// Sequential LIF scan, ONE barrier per step.
// Warp w owns neurons [32w, 32w+32). Lane l: q = l>>3 (group block of 8
// groups), ul = l&7 -> h-quad u = 8w+ul. Gather 8 table rows (LDG.128),
// combine the 4 quarter partials with shfl.bfly (same addition tree as the
// smem version -> bitwise identical), distribute via shfl.idx, LIF, ballot.
// Spike mask exchanged through double-buffered sbits words.
// ---------------------------------------------------------------------------
__global__ __launch_bounds__(H_, 1) void scan_kernel(
    const float* __restrict__ b_rec, float* __restrict__ out) {
    __shared__ uint2 sb[2][4];             // 8 ballot words per buffer

    const int b = blockIdx.x;
    const int tid = threadIdx.x;
    const int w = tid >> 5, lane = tid & 31;
    const int q = lane >> 3, ul = lane & 7;
    const int u = w * 8 + ul;              // h-quad for the gather phase
    const int h = tid;                     // neuron for the LIF phase
    const int c = lane & 3;
    const int srcl = lane >> 2;            // lane holding my quad's partial

    const float* pb = g_proj + (size_t)b * T_ * H_;
    float* ob = out + (size_t)b * T_ * H_;
    const float brec = b_rec[h];

    // table base: quarter q's 8 groups, at h-quad u
    const char* tbase = (const char*)g_tab
                      + ((size_t)q * 8 * NP * H_ * 4)
                      + (size_t)u * 16;

    if (tid < 8) ((unsigned*)sb[0])[tid] = 0u;
    __syncthreads();

    float mem = 0.0f, spk = 0.0f;
    int buf = 0;
    float p0 = pb[h];
    float p1 = pb[H_ + h];

    for (int t = 0; t < T_; t++) {
        float p2 = (t + 2 < T_) ? pb[(size_t)(t + 2) * H_ + h] : 0.0f;

        // ---- gather: 8 pattern-indexed table rows (ascending group order) ----
        const uint2 wp = sb[buf][q];
        float4 acc;
        {
            const float4 v0 = *(const float4*)(tbase + ((0u << 8) + ( wp.x        & 0xFFu)) * 1024u);
            const float4 v1 = *(const float4*)(tbase + ((1u << 8) + ((wp.x >>  8) & 0xFFu)) * 1024u);
            const float4 v2 = *(const float4*)(tbase + ((2u << 8) + ((wp.x >> 16) & 0xFFu)) * 1024u);
            const float4 v3 = *(const float4*)(tbase + ((3u << 8) + ((wp.x >> 24) & 0xFFu)) * 1024u);
            const float4 v4 = *(const float4*)(tbase + ((4u << 8) + ( wp.y        & 0xFFu)) * 1024u);
            const float4 v5 = *(const float4*)(tbase + ((5u << 8) + ((wp.y >>  8) & 0xFFu)) * 1024u);
            const float4 v6 = *(const float4*)(tbase + ((6u << 8) + ((wp.y >> 16) & 0xFFu)) * 1024u);
            const float4 v7 = *(const float4*)(tbase + ((7u << 8) + ((wp.y >> 24) & 0xFFu)) * 1024u);
            acc.x = __fadd_rn(__fadd_rn(__fadd_rn(__fadd_rn(__fadd_rn(__fadd_rn(__fadd_rn(v0.x, v1.x), v2.x), v3.x), v4.x), v5.x), v6.x), v7.x);
            acc.y = __fadd_rn(__fadd_rn(__fadd_rn(__fadd_rn(__fadd_rn(__fadd_rn(__fadd_rn(v0.y, v1.y), v2.y), v3.y), v4.y), v5.y), v6.y), v7.y);
            acc.z = __fadd_rn(__fadd_rn(__fadd_rn(__fadd_rn(__fadd_rn(__fadd_rn(__fadd_rn(v0.z, v1.z), v2.z), v3.z), v4.z), v5.z), v6.z), v7.z);
            acc.w = __fadd_rn(__fadd_rn(__fadd_rn(__fadd_rn(__fadd_rn(__fadd_rn(__fadd_rn(v0.w, v1.w), v2.w), v3.w), v4.w), v5.w), v6.w), v7.w);
        }

        // ---- butterfly over q (lanes xor 8, 16): tree (q0+q1)+(q2+q3) ----
        acc.x = __fadd_rn(acc.x, __shfl_xor_sync(0xFFFFFFFFu, acc.x, 8));
        acc.y = __fadd_rn(acc.y, __shfl_xor_sync(0xFFFFFFFFu, acc.y, 8));
        acc.z = __fadd_rn(acc.z, __shfl_xor_sync(0xFFFFFFFFu, acc.z, 8));
        acc.w = __fadd_rn(acc.w, __shfl_xor_sync(0xFFFFFFFFu, acc.w, 8));
        acc.x = __fadd_rn(acc.x, __shfl_xor_sync(0xFFFFFFFFu, acc.x, 16));
        acc.y = __fadd_rn(acc.y, __shfl_xor_sync(0xFFFFFFFFu, acc.y, 16));
        acc.z = __fadd_rn(acc.z, __shfl_xor_sync(0xFFFFFFFFu, acc.z, 16));
        acc.w = __fadd_rn(acc.w, __shfl_xor_sync(0xFFFFFFFFu, acc.w, 16));

        // ---- distribute: thread h needs quad (h>>2)'s partials ----
        const float sx = __shfl_sync(0xFFFFFFFFu, acc.x, srcl);
        const float sy = __shfl_sync(0xFFFFFFFFu, acc.y, srcl);
        const float sz = __shfl_sync(0xFFFFFFFFu, acc.z, srcl);
        const float sw = __shfl_sync(0xFFFFFFFFu, acc.w, srcl);
        float rec = (c == 0) ? sx : (c == 1) ? sy : (c == 2) ? sz : sw;
        rec = __fadd_rn(rec, brec);

        // ---- LIF update ----
        const float reset = (mem > 1.0f) ? 1.0f : 0.0f;
        const float in_ = __fadd_rn(p0, spk);
        mem = __fsub_rn(__fadd_rn(__fadd_rn(__fmul_rn(0.85f, mem), in_), rec), reset);
        const float s = (mem > 1.0f) ? 1.0f : 0.0f;
        ob[(size_t)t * H_ + h] = s;

        const unsigned ball = __ballot_sync(0xFFFFFFFFu, s != 0.0f);
        const int nb = buf ^ 1;
        if (lane == 0) ((unsigned*)sb[nb])[w] = ball;
        __syncthreads();

        buf = nb; spk = s;
        p0 = p1; p1 = p2;
    }
}

// ---------------------------------------------------------------------------
extern "C" void kernel_launch(void* const* d_in, const int* in_sizes, int n_in,
                              void* d_out, int out_size) {
    const float* x     = (const float*)d_in[0];
    const float* W_in  = (const float*)d_in[1];
    const float* b_in  = (const float*)d_in[2];
    const float* V     = (const float*)d_in[3];
    const float* b_rec = (const float*)d_in[4];
    float* out = (float*)d_out;

    transpose_V<<<H_, H_>>>(V);
    build_tab<<<NG * NP, H_>>>();
    gemm_proj<<<dim3((B_ * T_) / GBM, H_ / GBN), 256>>>(x, W_in, b_in);
    scan_kernel<<<B_, H_>>>(b_rec, out);
}

// round 7
// speedup vs baseline: 1.3353x; 1.3353x over previous
#include <cuda_runtime.h>
#include <cstdint>

#define B_  32
#define T_  2048
#define IN_ 512
#define H_  256
#define NG  32      // groups of 8 presynaptic neurons
#define NP  256     // patterns per group (2^8)
#define NCH 32      // T_/64 proj chunks per batch

#define NSCAN 32    // scan CTAs (one per batch)
#define NWORK 116   // persistent GEMM worker CTAs
#define NJOBS 2048  // (B_*T_/GM) * 2 n-halves

// Scratch (allocation-free rule: __device__ globals)
__device__ float g_proj[(size_t)B_ * T_ * H_];        // 64 MB input projection
__device__ float g_Vt[H_ * H_];                       // Vt[j][h] = V[h][j]
__device__ float g_tab[(size_t)NG * NP * H_];         // 8 MB group subset-sum table
__device__ unsigned g_flag[B_ * NCH];                 // producer->consumer chunk flags

// ---------------------------------------------------------------------------
// Setup kernels
// ---------------------------------------------------------------------------
__global__ void transpose_V(const float* __restrict__ V) {
    int j = blockIdx.x;
    int h = threadIdx.x;
    g_Vt[j * H_ + h] = V[h * H_ + j];
}

// tab[g][p][h] = sum_{i: bit i of p} Vt[8g+i][h]   (ascending i)
__global__ void build_tab(void) {
    const int blk = blockIdx.x;          // 0..8191
    const int g = blk >> 8;
    const int p = blk & 255;
    const int h = threadIdx.x;
    float s = 0.0f;
    #pragma unroll
    for (int i = 0; i < 8; i++)
        if ((p >> i) & 1)
            s = __fadd_rn(s, g_Vt[(g * 8 + i) * H_ + h]);
    g_tab[((size_t)g * NP + p) * H_ + h] = s;
}

__global__ void init_flags(void) {
    g_flag[threadIdx.x] = 0u;
}

// ---------------------------------------------------------------------------
// chunk-ready spin (acquire)
// ---------------------------------------------------------------------------
__device__ __forceinline__ void wait_chunk(const unsigned* f) {
    unsigned v;
    do {
        asm volatile("ld.acquire.gpu.global.u32 %0, [%1];"
                     : "=r"(v) : "l"(f) : "memory");
    } while (v < 2u);
}

// ---------------------------------------------------------------------------
// Fused persistent kernel.
//   CTA 0..31   : LIF scan for batch = blockIdx.x  (R4 structure)
//   CTA 32..147 : GEMM workers, grid-stride over NJOBS tile jobs,
//                 job jj: tc = jj>>6, b = (jj>>1)&31, nt = jj&1
//                 tile = proj[b, tc*64 .. tc*64+64) x [nt*128 .. nt*128+128)
// ---------------------------------------------------------------------------
#define GM 64
#define GN 128
#define GK 16

__global__ __launch_bounds__(256, 1) void fused_kernel(
    const float* __restrict__ x, const float* __restrict__ W,
    const float* __restrict__ bia,
    const float* __restrict__ b_rec, float* __restrict__ out) {

    __shared__ float As[2][GK][GM];       // GEMM buffers (worker role)
    __shared__ float Bs[2][GK][GN];
    __shared__ float4 sp[2][4][64];       // scan partials (scan role)
    __shared__ unsigned sbits[2][8];

    const int cta = blockIdx.x;
    const int tid = threadIdx.x;

    if (cta >= NSCAN) {
        // =================== GEMM worker role ===================
        const int tx = tid & 15;       // n-octet
        const int ty = tid >> 4;       // m-quad
        const int lr = tid >> 2;       // load row 0..63
        const int lc = (tid & 3) * 4;  // load col (float4)

        for (int jj = cta - NSCAN; jj < NJOBS; jj += NWORK) {
            const int nt = jj & 1;
            const int b  = (jj >> 1) & 31;
            const int tc = jj >> 6;
            const size_t m0 = (size_t)b * T_ + (size_t)tc * GM;
            const int bn = nt * GN;

            float acc[4][8];
            #pragma unroll
            for (int i = 0; i < 4; i++)
                #pragma unroll
                for (int j = 0; j < 8; j++) acc[i][j] = 0.0f;

            float4 ra, rb0, rb1;
            ra  = *(const float4*)&x[(m0 + lr) * IN_ + lc];
            rb0 = *(const float4*)&W[(size_t)(bn + lr) * IN_ + lc];
            rb1 = *(const float4*)&W[(size_t)(bn + 64 + lr) * IN_ + lc];
            As[0][lc + 0][lr] = ra.x;  As[0][lc + 1][lr] = ra.y;
            As[0][lc + 2][lr] = ra.z;  As[0][lc + 3][lr] = ra.w;
            Bs[0][lc + 0][lr] = rb0.x; Bs[0][lc + 1][lr] = rb0.y;
            Bs[0][lc + 2][lr] = rb0.z; Bs[0][lc + 3][lr] = rb0.w;
            Bs[0][lc + 0][lr + 64] = rb1.x; Bs[0][lc + 1][lr + 64] = rb1.y;
            Bs[0][lc + 2][lr + 64] = rb1.z; Bs[0][lc + 3][lr + 64] = rb1.w;
            __syncthreads();

            const int NT = IN_ / GK;   // 32
            for (int kt = 0; kt < NT; kt++) {
                const int cur = kt & 1, nxt = cur ^ 1;
                if (kt + 1 < NT) {
                    int k0 = (kt + 1) * GK + lc;
                    ra  = *(const float4*)&x[(m0 + lr) * IN_ + k0];
                    rb0 = *(const float4*)&W[(size_t)(bn + lr) * IN_ + k0];
                    rb1 = *(const float4*)&W[(size_t)(bn + 64 + lr) * IN_ + k0];
                }
                #pragma unroll
                for (int kk = 0; kk < GK; kk++) {
                    float a[4], bb[8];
                    *(float4*)&a[0]  = *(const float4*)&As[cur][kk][ty * 4];
                    *(float4*)&bb[0] = *(const float4*)&Bs[cur][kk][tx * 8];
                    *(float4*)&bb[4] = *(const float4*)&Bs[cur][kk][tx * 8 + 4];
                    #pragma unroll
                    for (int i = 0; i < 4; i++)
                        #pragma unroll
                        for (int j = 0; j < 8; j++)
                            acc[i][j] = fmaf(a[i], bb[j], acc[i][j]);
                }
                if (kt + 1 < NT) {
                    As[nxt][lc + 0][lr] = ra.x;  As[nxt][lc + 1][lr] = ra.y;
                    As[nxt][lc + 2][lr] = ra.z;  As[nxt][lc + 3][lr] = ra.w;
                    Bs[nxt][lc + 0][lr] = rb0.x; Bs[nxt][lc + 1][lr] = rb0.y;
                    Bs[nxt][lc + 2][lr] = rb0.z; Bs[nxt][lc + 3][lr] = rb0.w;
                    Bs[nxt][lc + 0][lr + 64] = rb1.x; Bs[nxt][lc + 1][lr + 64] = rb1.y;
                    Bs[nxt][lc + 2][lr + 64] = rb1.z; Bs[nxt][lc + 3][lr + 64] = rb1.w;
                }
                __syncthreads();
            }

            float bv[8];
            #pragma unroll
            for (int j = 0; j < 8; j++) bv[j] = bia[bn + tx * 8 + j];
            #pragma unroll
            for (int i = 0; i < 4; i++) {
                size_t m = m0 + ty * 4 + i;
                float4 o0, o1;
                o0.x = acc[i][0] + bv[0]; o0.y = acc[i][1] + bv[1];
                o0.z = acc[i][2] + bv[2]; o0.w = acc[i][3] + bv[3];
                o1.x = acc[i][4] + bv[4]; o1.y = acc[i][5] + bv[5];
                o1.z = acc[i][6] + bv[6]; o1.w = acc[i][7] + bv[7];
                *(float4*)&g_proj[m * H_ + bn + tx * 8]     = o0;
                *(float4*)&g_proj[m * H_ + bn + tx * 8 + 4] = o1;
            }

            // release this chunk (2 arrivals per chunk: nt=0 and nt=1)
            __syncthreads();
            if (tid == 0) {
                __threadfence();
                atomicAdd(&g_flag[b * NCH + tc], 1u);
            }
        }
        return;
    }

    // ======================= scan role =======================
    const int b = cta;
    const int h = tid;
    const int wid = tid >> 5, lane = tid & 31;
    const int q = tid >> 6, u = tid & 63;

    const float* pb = g_proj + (size_t)b * T_ * H_;
    float* ob = out + (size_t)b * T_ * H_;
    const float brec = b_rec[h];
    const unsigned* fb = g_flag + b * NCH;

    const char* tbase = (const char*)g_tab
                      + ((size_t)q * 8 * NP * H_ * 4)
                      + (size_t)u * 16;

    if (tid < 8) sbits[0][tid] = 0u;
    __syncthreads();

    // wait for first proj chunk, then seed the 2-deep prefetch pipeline
    if (tid == 0) wait_chunk(fb);
    __syncthreads();
    float mem = 0.0f, spk = 0.0f;
    int buf = 0;
    float p0 = pb[h];
    float p1 = pb[H_ + h];

    for (int t = 0; t < T_; t++) {
        const int tn = t + 2;
        if (tn < T_ && (tn & 63) == 0) {
            if (tid == 0) wait_chunk(fb + (tn >> 6));
            __syncthreads();
        }
        float p2 = (tn < T_) ? pb[(size_t)tn * H_ + h] : 0.0f;

        // ---- phase 1: table-row gather (groups ascending = j ascending) ----
        const unsigned wA = sbits[buf][2 * q];
        const unsigned wB = sbits[buf][2 * q + 1];
        float4 acc = make_float4(0.f, 0.f, 0.f, 0.f);
        #pragma unroll
        for (int i = 0; i < 8; i++) {
            unsigned pat = (i < 4) ? ((wA >> (8 * i)) & 0xFFu)
                                   : ((wB >> (8 * (i - 4))) & 0xFFu);
            const float4 v = *(const float4*)(tbase + (((unsigned)i << 8) + pat) * 1024u);
            acc.x = __fadd_rn(acc.x, v.x);
            acc.y = __fadd_rn(acc.y, v.y);
            acc.z = __fadd_rn(acc.z, v.z);
            acc.w = __fadd_rn(acc.w, v.w);
        }
        sp[buf][q][u] = acc;
        __syncthreads();   // A

        // ---- phase 2: combine quarters + LIF update ----
        const int uu = h >> 2, c = h & 3;
        const float r0 = ((const float*)&sp[buf][0][uu])[c];
        const float r1 = ((const float*)&sp[buf][1][uu])[c];
        const float r2 = ((const float*)&sp[buf][2][uu])[c];
        const float r3 = ((const float*)&sp[buf][3][uu])[c];
        float rec = __fadd_rn(__fadd_rn(r0, r1), __fadd_rn(r2, r3));
        rec = __fadd_rn(rec, brec);

        const float reset = (mem > 1.0f) ? 1.0f : 0.0f;
        const float in_ = __fadd_rn(p0, spk);
        mem = __fsub_rn(__fadd_rn(__fadd_rn(__fmul_rn(0.85f, mem), in_), rec), reset);
        const float s = (mem > 1.0f) ? 1.0f : 0.0f;
        ob[(size_t)t * H_ + h] = s;

        const unsigned ball = __ballot_sync(0xFFFFFFFFu, s != 0.0f);
        const int nb = buf ^ 1;
        if (lane == 0) sbits[nb][wid] = ball;
        __syncthreads();   // B

        buf = nb; spk = s;
        p0 = p1; p1 = p2;
    }
}

// ---------------------------------------------------------------------------
extern "C" void kernel_launch(void* const* d_in, const int* in_sizes, int n_in,
                              void* d_out, int out_size) {
    const float* x     = (const float*)d_in[0];
    const float* W_in  = (const float*)d_in[1];
    const float* b_in  = (const float*)d_in[2];
    const float* V     = (const float*)d_in[3];
    const float* b_rec = (const float*)d_in[4];
    float* out = (float*)d_out;

    transpose_V<<<H_, H_>>>(V);
    build_tab<<<NG * NP, H_>>>();
    init_flags<<<1, B_ * NCH>>>();
    fused_kernel<<<NSCAN + NWORK, 256>>>(x, W_in, b_in, b_rec, out);
}